// round 7
// baseline (speedup 1.0000x reference)
#include <cuda_runtime.h>
#include <cuda_bf16.h>
#include <cstdint>

#define NN   1024
#define NN2  (NN * NN)
#define BD   64
#define NB   128
#define ROWB 144         // 128B k-data (BK=64) + 16B pad

// ============================================================================
// Device global scratch (allocation-free rule)
// ============================================================================
__device__ __align__(16) __nv_bfloat16 g_St_hi[NN2], g_St_lo[NN2];
__device__ __align__(16) __nv_bfloat16 g_Ta_hi[NN2], g_Ta_lo[NN2];
__device__ __align__(16) __nv_bfloat16 g_Tb_hi[NN2], g_Tb_lo[NN2];
__device__ __align__(16) __nv_bfloat16 g_Xt_hi[(size_t)NB * BD * NN];
__device__ __align__(16) __nv_bfloat16 g_Xt_lo[(size_t)NB * BD * NN];
__device__ __align__(16) float g_part[4][NN2];

// ============================================================================
// PTX helpers (baseline sm_80-class, legal under compute_103)
// ============================================================================
__device__ __forceinline__ uint32_t smem_to_u32(const void* p) {
    uint32_t a;
    asm("{ .reg .u64 t; cvta.to.shared.u64 t, %1; cvt.u32.u64 %0, t; }"
        : "=r"(a) : "l"(p));
    return a;
}
__device__ __forceinline__ void cp16(uint32_t s, const void* g) {
    asm volatile("cp.async.cg.shared.global [%0], [%1], 16;" :: "r"(s), "l"(g));
}
#define CP_COMMIT() asm volatile("cp.async.commit_group;" ::: "memory")
#define CP_WAIT(n)  asm volatile("cp.async.wait_group %0;" :: "n"(n) : "memory")

__device__ __forceinline__ void ldsm4(uint32_t& r0, uint32_t& r1,
                                      uint32_t& r2, uint32_t& r3, uint32_t a) {
    asm volatile("ldmatrix.sync.aligned.m8n8.x4.shared.b16 {%0,%1,%2,%3}, [%4];"
                 : "=r"(r0), "=r"(r1), "=r"(r2), "=r"(r3) : "r"(a));
}
__device__ __forceinline__ void mma16816(float* c, const uint32_t* a,
                                         uint32_t b0, uint32_t b1) {
    asm volatile(
        "mma.sync.aligned.m16n8k16.row.col.f32.bf16.bf16.f32 "
        "{%0,%1,%2,%3}, {%4,%5,%6,%7}, {%8,%9}, {%0,%1,%2,%3};"
        : "+f"(c[0]), "+f"(c[1]), "+f"(c[2]), "+f"(c[3])
        : "r"(a[0]), "r"(a[1]), "r"(a[2]), "r"(a[3]), "r"(b0), "r"(b1));
}

__device__ __forceinline__ void split_bf16(float v, __nv_bfloat16& h, __nv_bfloat16& l) {
    h = __float2bfloat16(v);
    l = __float2bfloat16(v - __bfloat162float(h));
}

// ============================================================================
// Converts
// ============================================================================
__global__ __launch_bounds__(256) void convert_St(const float* __restrict__ S) {
    __shared__ float tile[64][65];
    int k0 = blockIdx.x * 64, n0 = blockIdx.y * 64;
    for (int idx = threadIdx.x; idx < 64 * 64; idx += 256) {
        int r = idx >> 6, c = idx & 63;
        tile[r][c] = S[(size_t)(k0 + r) * NN + n0 + c];
    }
    __syncthreads();
    for (int idx = threadIdx.x; idx < 64 * 64; idx += 256) {
        int r = idx >> 6, c = idx & 63;
        __nv_bfloat16 h, l; split_bf16(tile[c][r], h, l);
        size_t o = (size_t)(n0 + r) * NN + k0 + c;
        g_St_hi[o] = h; g_St_lo[o] = l;
    }
}
__global__ __launch_bounds__(256) void convert_X(const float* __restrict__ X) {
    __shared__ float tile[64][65];
    int k0 = blockIdx.x * 64, b = blockIdx.y;
    for (int idx = threadIdx.x; idx < 64 * 64; idx += 256) {
        int r = idx >> 6, c = idx & 63;
        tile[r][c] = X[((size_t)b * NN + k0 + r) * BD + c];
    }
    __syncthreads();
    for (int idx = threadIdx.x; idx < 64 * 64; idx += 256) {
        int r = idx >> 6, c = idx & 63;
        __nv_bfloat16 h, l; split_bf16(tile[c][r], h, l);
        size_t o = ((size_t)b * BD + r) * NN + k0 + c;
        g_Xt_hi[o] = h; g_Xt_lo[o] = l;
    }
}
__global__ __launch_bounds__(256) void convert_init(const float* __restrict__ W7) {
    size_t i = (size_t)blockIdx.x * 256 + threadIdx.x;
    __nv_bfloat16 h, l; split_bf16(W7[i], h, l);
    g_Ta_hi[i] = h; g_Ta_lo[i] = l;
}

// ============================================================================
// GEMM core: tile 128x128, 128 threads (4 warps, 2Mx2N, warp tile 64x64),
// BK=64, 3-stage cp.async ring. Stage = 256 rows x 144B = 36864 B.
// ============================================================================
#define STG_BYTES (256 * ROWB)
#define OP_SMEM   (3 * STG_BYTES)

#define LOAD_STAGE(Ap, Bp, k, slot)                                           \
    do {                                                                      \
        const uint32_t _base = sbase + (slot) * STG_BYTES;                    \
        _Pragma("unroll")                                                     \
        for (int _i = 0; _i < 16; ++_i) {                                     \
            int _idx = tid + _i * 128;                                        \
            int _r = _idx >> 3, _c = _idx & 7;                                \
            const __nv_bfloat16* _src = (_r < 128)                            \
                ? (Ap) + (size_t)(row0 + _r) * NN + (k) + _c * 8              \
                : (Bp) + (size_t)(col0 + _r - 128) * NN + (k) + _c * 8;       \
            cp16(_base + _r * ROWB + _c * 16, _src);                          \
        }                                                                     \
        CP_COMMIT();                                                          \
    } while (0)

#define LDS_A4(a, k16, sA)                                                    \
    _Pragma("unroll")                                                         \
    for (int _mt = 0; _mt < 4; ++_mt)                                         \
        ldsm4((a)[_mt][0], (a)[_mt][1], (a)[_mt][2], (a)[_mt][3],             \
              (sA) + (uint32_t)(wm + _mt * 16 + (lane & 15)) * ROWB           \
                   + (uint32_t)((k16) * 2 + (lane >> 4)) * 16)

#define LDS_B4(b, k16, sB)                                                    \
    _Pragma("unroll")                                                         \
    for (int _p = 0; _p < 4; ++_p)                                            \
        ldsm4((b)[_p][0], (b)[_p][1], (b)[_p][2], (b)[_p][3],                 \
              (sB) + (uint32_t)(wn + _p * 16 + ((lane >> 4) << 3) + (lane & 7)) * ROWB \
                   + (uint32_t)((k16) * 2 + ((lane >> 3) & 1)) * 16)

#define MMA_ALL4(acc, a, b)                                                   \
    _Pragma("unroll")                                                         \
    for (int _mt = 0; _mt < 4; ++_mt)                                         \
        _Pragma("unroll")                                                     \
        for (int _nt = 0; _nt < 8; ++_nt)                                     \
            mma16816((acc)[_mt][_nt], (a)[_mt],                               \
                     (b)[_nt >> 1][(_nt & 1) * 2], (b)[_nt >> 1][(_nt & 1) * 2 + 1])

// ============================================================================
// gemm_splitk: partial[z] = T(rows) @ S^T(cols) over K-chunk z (768 of 3072)
// grid (8, 8, 4) = 256 CTAs, 128 threads.
// ============================================================================
__global__ __launch_bounds__(128, 2)
void gemm_splitk(int inSel) {
    extern __shared__ __align__(16) char smem[];
    const int tid  = threadIdx.x;
    const int lane = tid & 31, w = tid >> 5;
    const int wm   = (w >> 1) * 64;
    const int wn   = (w & 1) * 64;
    const int row0 = blockIdx.y * 128;
    const int col0 = blockIdx.x * 128;
    const int kb   = blockIdx.z * 768;
    const uint32_t sbase = smem_to_u32(smem);

    const __nv_bfloat16* Ah = inSel ? g_Tb_hi : g_Ta_hi;
    const __nv_bfloat16* Al = inSel ? g_Tb_lo : g_Ta_lo;

    auto issue = [&](int s, int slot) {
        const int kk  = kb + s * 64;
        const int seg = kk >> 10;
        const int k   = kk & 1023;
        const __nv_bfloat16* Ap = (seg < 2) ? Ah : Al;
        const __nv_bfloat16* Bp = (seg == 1) ? g_St_lo : g_St_hi;
        LOAD_STAGE(Ap, Bp, k, slot);
    };

    float acc[4][8][4] = {};
    issue(0, 0); issue(1, 1);

    for (int s = 0; s < 12; ++s) {
        CP_WAIT(1);
        __syncthreads();
        const uint32_t sA = sbase + (s % 3) * STG_BYTES;
        const uint32_t sB = sA + 128 * ROWB;

        uint32_t a[4][4], b[4][4];
        LDS_A4(a, 0, sA); LDS_B4(b, 0, sB);
        if (s + 2 < 12) issue(s + 2, (s + 2) % 3); else CP_COMMIT();
        MMA_ALL4(acc, a, b);
        #pragma unroll
        for (int k16 = 1; k16 < 4; ++k16) {
            LDS_A4(a, k16, sA); LDS_B4(b, k16, sB);
            MMA_ALL4(acc, a, b);
        }
    }

    float* P = g_part[blockIdx.z];
    const int g  = lane >> 2;
    const int i2 = (lane & 3) * 2;
    #pragma unroll
    for (int mt = 0; mt < 4; ++mt)
        #pragma unroll
        for (int nt = 0; nt < 8; ++nt) {
            const int m0 = row0 + wm + mt * 16 + g;
            const int n  = col0 + wn + nt * 8 + i2;
            *(float2*)(P + (size_t)m0 * NN + n)       = make_float2(acc[mt][nt][0], acc[mt][nt][1]);
            *(float2*)(P + (size_t)(m0 + 8) * NN + n) = make_float2(acc[mt][nt][2], acc[mt][nt][3]);
        }
}

// ============================================================================
// reduce_split: T_next = split(sum(parts) + Wk)
// ============================================================================
__global__ __launch_bounds__(256)
void reduce_split(const float* __restrict__ Wk, int inSel) {
    __nv_bfloat16* Oh = inSel ? g_Ta_hi : g_Tb_hi;
    __nv_bfloat16* Ol = inSel ? g_Ta_lo : g_Tb_lo;
    size_t i = ((size_t)blockIdx.x * 256 + threadIdx.x) * 4;
    float4 p0 = *(const float4*)&g_part[0][i];
    float4 p1 = *(const float4*)&g_part[1][i];
    float4 p2 = *(const float4*)&g_part[2][i];
    float4 p3 = *(const float4*)&g_part[3][i];
    float4 wv = *(const float4*)&Wk[i];
    float v0 = p0.x + p1.x + p2.x + p3.x + wv.x;
    float v1 = p0.y + p1.y + p2.y + p3.y + wv.y;
    float v2 = p0.z + p1.z + p2.z + p3.z + wv.z;
    float v3 = p0.w + p1.w + p2.w + p3.w + wv.w;
    __nv_bfloat16 h0, l0, h1, l1, h2, l2, h3, l3;
    split_bf16(v0, h0, l0); split_bf16(v1, h1, l1);
    split_bf16(v2, h2, l2); split_bf16(v3, h3, l3);
    __nv_bfloat162 a, bq;
    a.x = h0; a.y = h1; bq.x = h2; bq.y = h3;
    *(__nv_bfloat162*)(Oh + i)     = a;
    *(__nv_bfloat162*)(Oh + i + 2) = bq;
    a.x = l0; a.y = l1; bq.x = l2; bq.y = l3;
    *(__nv_bfloat162*)(Ol + i)     = a;
    *(__nv_bfloat162*)(Ol + i + 2) = bq;
}

// ============================================================================
// gemm_final: out = A_final @ Xcat   grid (64, 8) = 512 CTAs, 128 threads.
// ============================================================================
__global__ __launch_bounds__(128, 2)
void gemm_final(float* __restrict__ outp) {
    extern __shared__ __align__(16) char smem[];
    const int tid  = threadIdx.x;
    const int lane = tid & 31, w = tid >> 5;
    const int wm   = (w >> 1) * 64;
    const int wn   = (w & 1) * 64;
    const int row0 = blockIdx.y * 128;
    const int col0 = blockIdx.x * 128;     // global column in [0, 8192)
    const uint32_t sbase = smem_to_u32(smem);

    auto issue = [&](int s, int slot) {
        const int kk  = s * 64;
        const int seg = kk >> 10;
        const int k   = kk & 1023;
        const __nv_bfloat16* Ap = (seg < 2) ? g_Tb_hi : g_Tb_lo;
        const __nv_bfloat16* Bp = (seg == 1) ? g_Xt_lo : g_Xt_hi;
        LOAD_STAGE(Ap, Bp, k, slot);
    };

    float acc[4][8][4] = {};
    issue(0, 0); issue(1, 1);

    for (int s = 0; s < 48; ++s) {
        CP_WAIT(1);
        __syncthreads();
        const uint32_t sA = sbase + (s % 3) * STG_BYTES;
        const uint32_t sB = sA + 128 * ROWB;

        uint32_t a[4][4], b[4][4];
        LDS_A4(a, 0, sA); LDS_B4(b, 0, sB);
        if (s + 2 < 48) issue(s + 2, (s + 2) % 3); else CP_COMMIT();
        MMA_ALL4(acc, a, b);
        #pragma unroll
        for (int k16 = 1; k16 < 4; ++k16) {
            LDS_A4(a, k16, sA); LDS_B4(b, k16, sB);
            MMA_ALL4(acc, a, b);
        }
    }

    const int g  = lane >> 2;
    const int i2 = (lane & 3) * 2;
    #pragma unroll
    for (int mt = 0; mt < 4; ++mt)
        #pragma unroll
        for (int nt = 0; nt < 8; ++nt) {
            const int m0    = row0 + wm + mt * 16 + g;
            const int ncolg = col0 + wn + nt * 8 + i2;
            const int batch = ncolg >> 6;
            const int d     = ncolg & 63;
            float* o0 = outp + ((size_t)batch * NN + m0) * BD + d;
            float* o1 = outp + ((size_t)batch * NN + m0 + 8) * BD + d;
            *(float2*)o0 = make_float2(acc[mt][nt][0], acc[mt][nt][1]);
            *(float2*)o1 = make_float2(acc[mt][nt][2], acc[mt][nt][3]);
        }
}

// ============================================================================
// Host orchestration:
//   T = W7; for k = 6..0: T = T @ S + Wk (splitk x4 + reduce); out = T @ X
// ============================================================================
extern "C" void kernel_launch(void* const* d_in, const int* in_sizes, int n_in,
                              void* d_out, int out_size) {
    const float* nodes  = (const float*)d_in[0];   // [128, 1024, 64]
    const float* weight = (const float*)d_in[1];   // [8, 1024, 1024]
    const float* S      = (const float*)d_in[2];   // [1024, 1024]
    float* out = (float*)d_out;                    // [128, 1024, 64]

    cudaFuncSetAttribute(gemm_splitk, cudaFuncAttributeMaxDynamicSharedMemorySize, OP_SMEM);
    cudaFuncSetAttribute(gemm_final,  cudaFuncAttributeMaxDynamicSharedMemorySize, OP_SMEM);

    convert_St  <<<dim3(16, 16), 256>>>(S);
    convert_X   <<<dim3(16, NB), 256>>>(nodes);
    convert_init<<<NN2 / 256, 256>>>(weight + (size_t)7 * NN2);

    for (int step = 0; step < 7; ++step) {
        int inSel = step & 1;  // 0: read Ta (write Tb), 1: read Tb (write Ta)
        gemm_splitk <<<dim3(8, 8, 4), 128, OP_SMEM>>>(inSel);
        reduce_split<<<NN2 / 1024, 256>>>(weight + (size_t)(6 - step) * NN2, inSel);
    }
    // 7 steps: final operator lands in Tb
    gemm_final<<<dim3(64, 8), 128, OP_SMEM>>>(out);
}